// round 17
// baseline (speedup 1.0000x reference)
#include <cuda_runtime.h>
#include <cuda_fp16.h>
#include <math.h>
#include <stdint.h>

#define NN    30000
#define DMAXN 16
#define INF   128
#define HIDF  256

typedef uint32_t u32;

// ---------------- fp16 packed layout: 32-k groups of 16 u32 words ------------
// group word gw: qd=gw>>2, r=gw&3, chunk c=r>>1, v=(qd<<1)|(r&1);
//   v even -> k={v,v+1}, v odd -> k={v+7,v+8}   (within 16-k chunk, +16c)
// => LDS.128 at word 4*tig loads a thread's A/B fragment for BOTH chunks.
__device__ __forceinline__ int wpos16(int jc) {   // jc = even k index
    const int g = jc >> 5, kk = jc & 31, c = kk >> 4, k16 = kk & 15;
    const int v = (k16 < 8) ? k16 : k16 - 7;
    return (g << 4) | ((v >> 1) << 2) | (c << 1) | (v & 1);
}

__device__ __forceinline__ u32 packh2(float lo, float hi) {
    u32 r;
    asm("{ .reg .f16 l, h; cvt.rn.f16.f32 l, %1; cvt.rn.f16.f32 h, %2;"
        " mov.b32 %0, {l, h}; }" : "=r"(r) : "f"(lo), "f"(hi));
    return r;
}
__device__ __forceinline__ void mma16(float* d, u32 a0, u32 a1, u32 a2, u32 a3,
                                      u32 b0, u32 b1) {
    asm volatile("mma.sync.aligned.m16n8k16.row.col.f32.f16.f16.f32 "
                 "{%0,%1,%2,%3}, {%4,%5,%6,%7}, {%8,%9}, {%0,%1,%2,%3};"
                 : "+f"(d[0]), "+f"(d[1]), "+f"(d[2]), "+f"(d[3])
                 : "r"(a0), "r"(a1), "r"(a2), "r"(a3), "r"(b0), "r"(b1));
}
__device__ __forceinline__ u32 smem_u32(const void* p) {
    return (u32)__cvta_generic_to_shared(p);
}
__device__ __forceinline__ void cpa16(u32 d, const void* s) {
    asm volatile("cp.async.cg.shared.global [%0], [%1], 16;" :: "r"(d), "l"(s));
}
__device__ __forceinline__ void cpa_commit() {
    asm volatile("cp.async.commit_group;");
}
template <int N> __device__ __forceinline__ void cpa_wait() {
    asm volatile("cp.async.wait_group %0;" :: "n"(N));
}
__device__ __forceinline__ float sigmoid_f(float x) {
    return __fdividef(1.f, 1.f + __expf(-x));
}
__device__ __forceinline__ float tanh_f(float x) {
    float ax = fabsf(x);
    float e = __expf(-2.f * ax);
    return copysignf(__fdividef(1.f - e, 1.f + e), x);
}

// ---------------- scratch (device globals) -----------------------------------
__device__ u32   d_featq[NN * INF / 2];
__device__ u32   d_houtq[NN * HIDF / 2];
__device__ u32   d_h1q[2][NN * INF / 2];
__device__ u32   d_h2q[2][NN * HIDF / 2];
__device__ float d_c1[NN * INF];          // written at t=0 before any read
__device__ float d_c2[NN * HIDF];
// gx layout: [node][j/2][gate 0..3][2]  (gate-interleaved, fp32)
__device__ float d_gx1[NN * 4 * INF];
__device__ float d_gx2[NN * 4 * HIDF];
__device__ u32   d_Wih1q[4 * INF * INF / 2];
__device__ u32   d_Whh1q[4 * INF * INF / 2];
__device__ u32   d_Wih2q[4 * HIDF * HIDF / 2];
__device__ u32   d_Whh2q[4 * HIDF * HIDF / 2];
__device__ u32   d_Ws1q[HIDF * INF / 2];
__device__ u32   d_Wn1q[HIDF * INF / 2];
__device__ u32   d_Ws2q[64 * HIDF / 2];
__device__ u32   d_Wn2q[64 * HIDF / 2];
__device__ int   d_perm[NN];
__device__ int   d_rank[NN];
__device__ int   d_ofs[DMAXN + 2];
__device__ int   d_Kt[DMAXN + 1];

// ---------------- sort prep (hist + scan, single block) ----------------------
__global__ void sort_prep_k(const int* __restrict__ deg, int n) {
    __shared__ int cnt[DMAXN + 2];
    const int tid = threadIdx.x;
    if (tid < DMAXN + 2) cnt[tid] = 0;
    __syncthreads();
    for (int i = tid; i < n; i += blockDim.x) atomicAdd(&cnt[deg[i]], 1);
    __syncthreads();
    if (tid == 0) {
        int ofs[DMAXN + 2];
        int run = 0;
        for (int d = DMAXN; d >= 1; --d) { ofs[d] = run; run += cnt[d]; }
        for (int d = 1; d <= DMAXN; ++d) d_ofs[d] = ofs[d];
        for (int t = 0; t < DMAXN; ++t) d_Kt[t] = ofs[t + 1] + cnt[t + 1];
    }
}
__global__ void sort_scatter_k(const int* __restrict__ deg, int n) {
    int i = blockIdx.x * blockDim.x + threadIdx.x;
    if (i < n) {
        int p = atomicAdd(&d_ofs[deg[i]], 1);
        d_perm[p] = i;
        d_rank[i] = p;
    }
}

// ---------------- fp32 -> fp16, 32-k interleaved layout, all operands --------
__global__ void convert_all_k(const float* s0, int n0, const float* s1, int n1,
                              const float* s2, int n2, const float* s3, int n3,
                              const float* s4, int n4, const float* s5, int n5,
                              const float* s6, int n6, const float* s7, int n7,
                              const float* s8, int n8)
{
    const float* srcs[9] = {s0, s1, s2, s3, s4, s5, s6, s7, s8};
    u32* dsts[9] = {d_featq, d_Wih1q, d_Whh1q, d_Wih2q, d_Whh2q,
                    d_Ws1q, d_Wn1q, d_Ws2q, d_Wn2q};
    int lens[9] = {n0 / 2, n1 / 2, n2 / 2, n3 / 2, n4 / 2,
                   n5 / 2, n6 / 2, n7 / 2, n8 / 2};
    int total = 0;
#pragma unroll
    for (int s = 0; s < 9; s++) total += lens[s];

    const int stride = gridDim.x * blockDim.x;
    for (int g = blockIdx.x * blockDim.x + threadIdx.x; g < total; g += stride) {
        int i = g, s = 0;
#pragma unroll
        for (int j = 0; j < 8; j++)
            if (i >= lens[s]) { i -= lens[s]; s++; }
        const int grp = i >> 4, gw = i & 15;
        const int qd = gw >> 2, r = gw & 3;
        const int c = r >> 1, v = (qd << 1) | (r & 1);
        const int k16 = (v & 1) ? v + 7 : v;
        const int k0 = (grp << 5) + (c << 4) + k16;
        dsts[s][i] = packh2(srcs[s][k0], srcs[s][k0 + 1]);
    }
}

// ---------------- mma tile over a 32-k stage: 12 LDS.128, 32 HMMA ------------
template <int NFRW>
__device__ __forceinline__ void mma_tile2(const u32 (*__restrict__ As)[16],
                                          const u32 (*__restrict__ Bs)[16],
                                          float (*acc)[NFRW][4],
                                          int wm, int wn, int q, int tig)
{
    uint4 bv[NFRW];
#pragma unroll
    for (int nf = 0; nf < NFRW; nf++)
        bv[nf] = *(const uint4*)&Bs[wn * (8 * NFRW) + nf * 8 + q][4 * tig];
#pragma unroll
    for (int mf = 0; mf < 4; mf++) {
        const uint4 alo = *(const uint4*)&As[wm * 64 + mf * 16 + q][4 * tig];
        const uint4 ahi = *(const uint4*)&As[wm * 64 + mf * 16 + q + 8][4 * tig];
#pragma unroll
        for (int nf = 0; nf < NFRW; nf++) {
            mma16(acc[mf][nf], alo.x, ahi.x, alo.y, ahi.y, bv[nf].x, bv[nf].y);
            mma16(acc[mf][nf], alo.z, ahi.z, alo.w, ahi.w, bv[nf].z, bv[nf].w);
        }
    }
}

// ============================================================================
// gx = A @ W^T + (bih+bhh), gate-interleaved fp32 out. B rows gate-regrouped.
// ============================================================================
template <int K, int SRC>
__global__ __launch_bounds__(256, 2)
void mma_gx_k(const float* __restrict__ bih, const float* __restrict__ bhh, int n)
{
    const int r0 = blockIdx.x * 128;
    if (r0 >= n) return;
    const int j0 = blockIdx.y * 32;
    constexpr int NST = K / 32;
    constexpr int KW = K / 2;
    constexpr int M4 = 4 * K;
    constexpr int ABUF = 128 * 16;          // u32 per stage

    extern __shared__ __align__(16) u32 dsm[];
    u32* Asm = dsm;                          // [4][128][16]
    u32* Bsm = dsm + 4 * ABUF;

    const u32* A  = (SRC == 1) ? d_featq : d_houtq;
    const u32* Wq = (SRC == 1) ? d_Wih1q : d_Wih2q;
    float* out    = (SRC == 1) ? d_gx1 : d_gx2;

    const int tid = threadIdx.x;
    const int w = tid >> 5, lane = tid & 31;
    const int q = lane >> 2, tig = lane & 3;
    const int wm = w >> 2, wn = w & 3;

    const int crow = tid >> 1;
    const int seg2 = (tid & 1) * 2;
    const int rb = (crow >> 1) & 1;
    const int qd1 = seg2 + rb, qd2 = seg2 + (rb ^ 1);
    int ra = r0 + crow; if (ra > n - 1) ra = n - 1;
    const u32* pa = A + (size_t)ra * KW;
    const int wr = ((crow >> 3) & 3) * K + j0 + (crow & 7) + ((crow >> 5) << 3);
    const u32* pb = Wq + (size_t)wr * KW;

    const u32 smA = smem_u32(Asm) + crow * 64;
    const u32 smB = smem_u32(Bsm) + crow * 64;

    float acc[4][4][4];
#pragma unroll
    for (int i = 0; i < 4; i++)
#pragma unroll
        for (int j = 0; j < 4; j++)
#pragma unroll
            for (int c = 0; c < 4; c++) acc[i][j][c] = 0.f;

    auto issue = [&](int s) {
        if (s < NST) {
            const u32 off = (u32)(s & 3) * (ABUF * 4);
            const u32* ga = pa + s * 16;
            const u32* gb = pb + s * 16;
            cpa16(smA + off + qd1 * 16, ga + 4 * qd1);
            cpa16(smA + off + qd2 * 16, ga + 4 * qd2);
            cpa16(smB + off + qd1 * 16, gb + 4 * qd1);
            cpa16(smB + off + qd2 * 16, gb + 4 * qd2);
        }
        cpa_commit();
    };
    issue(0); issue(1); issue(2);

#pragma unroll 1
    for (int s = 0; s < NST; s++) {
        cpa_wait<2>();
        __syncthreads();
        issue(s + 3);
        mma_tile2<4>((const u32(*)[16])(Asm + (s & 3) * ABUF),
                     (const u32(*)[16])(Bsm + (s & 3) * ABUF),
                     acc, wm, wn, q, tig);
    }

    const int jc = j0 + wn * 8 + 2 * tig;
    float2 bsum[4];
#pragma unroll
    for (int g = 0; g < 4; g++)
        bsum[g] = make_float2(bih[g * K + jc] + bhh[g * K + jc],
                              bih[g * K + jc + 1] + bhh[g * K + jc + 1]);

#pragma unroll
    for (int mf = 0; mf < 4; mf++)
#pragma unroll
        for (int half = 0; half < 2; half++) {
            const int r = r0 + wm * 64 + mf * 16 + q + half * 8;
            if (r >= n) continue;
            float* op = out + (size_t)r * M4 + ((jc >> 1) << 3);
            *(float4*)(op) = make_float4(
                acc[mf][0][half * 2]     + bsum[0].x,
                acc[mf][0][half * 2 + 1] + bsum[0].y,
                acc[mf][1][half * 2]     + bsum[1].x,
                acc[mf][1][half * 2 + 1] + bsum[1].y);
            *(float4*)(op + 4) = make_float4(
                acc[mf][2][half * 2]     + bsum[2].x,
                acc[mf][2][half * 2 + 1] + bsum[2].y,
                acc[mf][3][half * 2]     + bsum[3].x,
                acc[mf][3][half * 2 + 1] + bsum[3].y);
        }
}

// ============================================================================
// Fused LSTM step: gates = h_{t-1} @ Whh^T + gx[nbr] (biases folded into gx).
// ============================================================================
template <int H, int LAYER>
__global__ __launch_bounds__(256, 2)
void mma_lstm_k(const int* __restrict__ nbr_idx, int t, int n)
{
    const int Kt = d_Kt[t];
    const int r0 = blockIdx.x * 128;
    if (r0 >= Kt) return;
    const int j0 = blockIdx.y * 32;
    constexpr int NST = H / 32;
    constexpr int HW = H / 2;
    constexpr int ABUF = 128 * 16;

    extern __shared__ __align__(16) u32 dsm[];
    u32* Asm = dsm;
    u32* Bsm = dsm + 4 * ABUF;
    __shared__ int s_nbr[128];

    const float* gx  = (LAYER == 1) ? d_gx1 : d_gx2;
    const u32* hread = (LAYER == 1) ? d_h1q[t & 1] : d_h2q[t & 1];
    u32*      hwrite = (LAYER == 1) ? d_h1q[(t + 1) & 1] : d_h2q[(t + 1) & 1];
    float*    cst    = (LAYER == 1) ? d_c1 : d_c2;
    const u32* Wq    = (LAYER == 1) ? d_Whh1q : d_Whh2q;

    const int tid = threadIdx.x;
    const int w = tid >> 5, lane = tid & 31;
    const int q = lane >> 2, tig = lane & 3;
    const int wm = w >> 2, wn = w & 3;

    if (tid < 128) {
        int r = r0 + tid; if (r > Kt - 1) r = Kt - 1;
        s_nbr[tid] = nbr_idx[d_perm[r] * DMAXN + t];
    }

    float acc[4][4][4];
#pragma unroll
    for (int i = 0; i < 4; i++)
#pragma unroll
        for (int j = 0; j < 4; j++)
#pragma unroll
            for (int c = 0; c < 4; c++) acc[i][j][c] = 0.f;

    if (t > 0) {
        const int crow = tid >> 1;
        const int seg2 = (tid & 1) * 2;
        const int rb = (crow >> 1) & 1;
        const int qd1 = seg2 + rb, qd2 = seg2 + (rb ^ 1);
        int ra = r0 + crow; if (ra > n - 1) ra = n - 1;
        const u32* pa = hread + (size_t)ra * HW;
        const int wr = ((crow >> 3) & 3) * H + j0 + (crow & 7) + ((crow >> 5) << 3);
        const u32* pb = Wq + (size_t)wr * HW;

        const u32 smA = smem_u32(Asm) + crow * 64;
        const u32 smB = smem_u32(Bsm) + crow * 64;

        auto issue = [&](int s) {
            if (s < NST) {
                const u32 off = (u32)(s & 3) * (ABUF * 4);
                const u32* ga = pa + s * 16;
                const u32* gb = pb + s * 16;
                cpa16(smA + off + qd1 * 16, ga + 4 * qd1);
                cpa16(smA + off + qd2 * 16, ga + 4 * qd2);
                cpa16(smB + off + qd1 * 16, gb + 4 * qd1);
                cpa16(smB + off + qd2 * 16, gb + 4 * qd2);
            }
            cpa_commit();
        };
        issue(0); issue(1); issue(2);

#pragma unroll 1
        for (int s = 0; s < NST; s++) {
            cpa_wait<2>();
            __syncthreads();
            issue(s + 3);
            mma_tile2<4>((const u32(*)[16])(Asm + (s & 3) * ABUF),
                         (const u32(*)[16])(Bsm + (s & 3) * ABUF),
                         acc, wm, wn, q, tig);
        }
    }
    __syncthreads();

    // ---- fused cell update; gx gate-interleaved ----
    const int jc = j0 + wn * 8 + 2 * tig;
    const int hwoff = wpos16(jc);
#pragma unroll
    for (int mf = 0; mf < 4; mf++)
#pragma unroll
        for (int half = 0; half < 2; half++) {
            const int lr = wm * 64 + mf * 16 + q + half * 8;
            const int r = r0 + lr;
            if (r >= Kt) continue;
            const int nbr = s_nbr[lr];
            const float* gp = gx + (size_t)nbr * (4 * H) + ((jc >> 1) << 3);
            const float4 gIF = *(const float4*)(gp);
            const float4 gGO = *(const float4*)(gp + 4);
            float2 cold = make_float2(0.f, 0.f);
            if (t > 0) cold = *(const float2*)(cst + (size_t)r * H + jc);
            float cn[2], hn[2];
#pragma unroll
            for (int b = 0; b < 2; b++) {
                const float gi = acc[mf][0][half * 2 + b] + (b ? gIF.y : gIF.x);
                const float gf = acc[mf][1][half * 2 + b] + (b ? gIF.w : gIF.z);
                const float gg = acc[mf][2][half * 2 + b] + (b ? gGO.y : gGO.x);
                const float go = acc[mf][3][half * 2 + b] + (b ? gGO.w : gGO.z);
                const float cv = sigmoid_f(gf) * (b ? cold.y : cold.x)
                               + sigmoid_f(gi) * tanh_f(gg);
                cn[b] = cv;
                hn[b] = sigmoid_f(go) * tanh_f(cv);
            }
            *(float2*)(cst + (size_t)r * H + jc) = make_float2(cn[0], cn[1]);
            hwrite[(size_t)r * HW + hwoff] = packh2(hn[0], hn[1]);
        }
}

// ============================================================================
// Fused FC: out = act(A1 @ W1^T + m @ W2^T + b), K = K1+K2 concat.
// ============================================================================
template <int K1, int K2, int NOUT, int BLKN, int LAYER>
__global__ __launch_bounds__(256, 2)
void mma_fc_k(const int* __restrict__ deg, const float* __restrict__ bias,
              float* __restrict__ outp, int n)
{
    const int r0 = blockIdx.x * 128;
    if (r0 >= n) return;
    const int n0 = blockIdx.y * BLKN;
    constexpr int NST = (K1 + K2) / 32;
    constexpr int NST1 = K1 / 32;
    constexpr int NFRW = BLKN / 32;
    constexpr int K1W = K1 / 2, K2W = K2 / 2;
    constexpr int ABUF = 128 * 16;
    constexpr int BBUF = BLKN * 16;

    extern __shared__ __align__(16) u32 dsm[];
    u32* Asm = dsm;
    u32* Bsm = dsm + 4 * ABUF;

    const u32* A1 = (LAYER == 1) ? d_featq : d_houtq;
    const u32* W1 = (LAYER == 1) ? d_Ws1q : d_Ws2q;
    const u32* W2 = (LAYER == 1) ? d_Wn1q : d_Wn2q;

    const int tid = threadIdx.x;
    const int w = tid >> 5, lane = tid & 31;
    const int q = lane >> 2, tig = lane & 3;
    const int wm = w >> 2, wn = w & 3;

    const int crow = tid >> 1;
    const int seg2 = (tid & 1) * 2;
    const int rb = (crow >> 1) & 1;
    const int qd1 = seg2 + rb, qd2 = seg2 + (rb ^ 1);
    int ra = r0 + crow; if (ra > n - 1) ra = n - 1;
    const u32* p1 = A1 + (size_t)ra * K1W;
    const u32* hb = (LAYER == 1) ? d_h1q[deg[ra] & 1] : d_h2q[deg[ra] & 1];
    const u32* p2 = hb + (size_t)d_rank[ra] * K2W;
    const bool bact = (tid < 2 * BLKN);
    const int brow = crow & (BLKN - 1);
    const u32* q1 = W1 + (size_t)(n0 + brow) * K1W;
    const u32* q2 = W2 + (size_t)(n0 + brow) * K2W;

    const u32 smA = smem_u32(Asm) + crow * 64;
    const u32 smB = smem_u32(Bsm) + brow * 64;

    float acc[4][NFRW][4];
#pragma unroll
    for (int i = 0; i < 4; i++)
#pragma unroll
        for (int j = 0; j < NFRW; j++)
#pragma unroll
            for (int c = 0; c < 4; c++) acc[i][j][c] = 0.f;

    auto issue = [&](int s) {
        if (s < NST) {
            const u32 offA = (u32)(s & 3) * (ABUF * 4);
            const u32 offB = (u32)(s & 3) * (BBUF * 4);
            const u32* ga = (s < NST1) ? (p1 + s * 16) : (p2 + (s - NST1) * 16);
            cpa16(smA + offA + qd1 * 16, ga + 4 * qd1);
            cpa16(smA + offA + qd2 * 16, ga + 4 * qd2);
            if (bact) {
                const u32* gb = (s < NST1) ? (q1 + s * 16)
                                           : (q2 + (s - NST1) * 16);
                cpa16(smB + offB + qd1 * 16, gb + 4 * qd1);
                cpa16(smB + offB + qd2 * 16, gb + 4 * qd2);
            }
        }
        cpa_commit();
    };
    issue(0); issue(1); issue(2);

#pragma unroll 1
    for (int s = 0; s < NST; s++) {
        cpa_wait<2>();
        __syncthreads();
        issue(s + 3);
        mma_tile2<NFRW>((const u32(*)[16])(Asm + (s & 3) * ABUF),
                        (const u32(*)[16])(Bsm + (s & 3) * BBUF),
                        acc, wm, wn, q, tig);
    }

    float2 bv2[NFRW];
#pragma unroll
    for (int nf = 0; nf < NFRW; nf++) {
        const int col = n0 + wn * (8 * NFRW) + nf * 8 + 2 * tig;
        bv2[nf] = make_float2(bias[col], bias[col + 1]);
    }
#pragma unroll
    for (int mf = 0; mf < 4; mf++)
#pragma unroll
        for (int half = 0; half < 2; half++) {
            const int r = r0 + wm * 64 + mf * 16 + q + half * 8;
            if (r >= n) continue;
#pragma unroll
            for (int nf = 0; nf < NFRW; nf++) {
                const int col = n0 + wn * (8 * NFRW) + nf * 8 + 2 * tig;
                float v0 = acc[mf][nf][half * 2]     + bv2[nf].x;
                float v1 = acc[mf][nf][half * 2 + 1] + bv2[nf].y;
                if (LAYER == 1) {
                    v0 = fmaxf(v0, 0.f); v1 = fmaxf(v1, 0.f);
                    d_houtq[(size_t)r * (NOUT / 2) + wpos16(col)] =
                        packh2(v0, v1);
                } else {
                    *(float2*)(outp + (size_t)r * NOUT + col) = make_float2(v0, v1);
                }
            }
        }
}

// ---------------- launch ----------------------------------------------------
extern "C" void kernel_launch(void* const* d_in, const int* in_sizes, int n_in,
                              void* d_out, int out_size)
{
    const float* feat    = (const float*)d_in[0];
    const int*   nbr     = (const int*)d_in[1];
    const int*   deg     = (const int*)d_in[2];
    const float* Wih1    = (const float*)d_in[3];
    const float* Whh1    = (const float*)d_in[4];
    const float* bih1    = (const float*)d_in[5];
    const float* bhh1    = (const float*)d_in[6];
    const float* Wself1  = (const float*)d_in[7];
    const float* Wneigh1 = (const float*)d_in[8];
    const float* b1      = (const float*)d_in[9];
    const float* Wih2    = (const float*)d_in[10];
    const float* Whh2    = (const float*)d_in[11];
    const float* bih2    = (const float*)d_in[12];
    const float* bhh2    = (const float*)d_in[13];
    const float* Wself2  = (const float*)d_in[14];
    const float* Wneigh2 = (const float*)d_in[15];
    const float* b2      = (const float*)d_in[16];

    const int n  = in_sizes[2];           // = N
    const int rb = (n + 127) / 128;

    const int SM64 = 4 * 128 * 16 * 4 * 2;          // 64 KB (A+B, 4 stages)
    const int SM48 = 4 * 128 * 16 * 4 + 4 * 64 * 16 * 4;  // FC2 (BLKN=64)
    cudaFuncSetAttribute(mma_gx_k<128, 1>,
                         cudaFuncAttributeMaxDynamicSharedMemorySize, SM64);
    cudaFuncSetAttribute(mma_gx_k<256, 2>,
                         cudaFuncAttributeMaxDynamicSharedMemorySize, SM64);
    cudaFuncSetAttribute(mma_lstm_k<128, 1>,
                         cudaFuncAttributeMaxDynamicSharedMemorySize, SM64);
    cudaFuncSetAttribute(mma_lstm_k<256, 2>,
                         cudaFuncAttributeMaxDynamicSharedMemorySize, SM64);
    cudaFuncSetAttribute((mma_fc_k<128, 128, 256, 128, 1>),
                         cudaFuncAttributeMaxDynamicSharedMemorySize, SM64);
    cudaFuncSetAttribute((mma_fc_k<256, 256, 64, 64, 2>),
                         cudaFuncAttributeMaxDynamicSharedMemorySize, SM48);

    sort_prep_k<<<1, 1024>>>(deg, n);
    sort_scatter_k<<<(n + 255) / 256, 256>>>(deg, n);

    convert_all_k<<<1024, 256>>>(feat, in_sizes[0], Wih1, in_sizes[3],
                                 Whh1, in_sizes[4], Wih2, in_sizes[10],
                                 Whh2, in_sizes[11], Wself1, in_sizes[7],
                                 Wneigh1, in_sizes[8], Wself2, in_sizes[14],
                                 Wneigh2, in_sizes[15]);

    // layer 1
    mma_gx_k<128, 1><<<dim3(rb, 4), 256, SM64>>>(bih1, bhh1, n);
    for (int t = 0; t < 16; t++)
        mma_lstm_k<128, 1><<<dim3(rb, 4), 256, SM64>>>(nbr, t, n);
    mma_fc_k<128, 128, 256, 128, 1><<<dim3(rb, 2), 256, SM64>>>(deg, b1,
                                                                nullptr, n);

    // layer 2
    mma_gx_k<256, 2><<<dim3(rb, 8), 256, SM64>>>(bih2, bhh2, n);
    for (int t = 0; t < 16; t++)
        mma_lstm_k<256, 2><<<dim3(rb, 8), 256, SM64>>>(nbr, t, n);
    mma_fc_k<256, 256, 64, 64, 2><<<dim3(rb, 1), 256, SM48>>>(deg, b2,
                                                              (float*)d_out, n);
}